// round 14
// baseline (speedup 1.0000x reference)
#include <cuda_runtime.h>
#include <cuda_bf16.h>
#include <cstdint>

#define B 384
#define D 128
#define TS 32                   // Gram tile size
#define GT (B / TS)             // 12 tiles per dim
#define NBLK1 (GT * GT)         // 144 gram blocks (single wave)
#define THR1 256
#define HP4 17                  // half-row pitch in float4 (16 + 1 pad)
#define NA 3
#define NB (B / NA)             // 128 triplet blocks
#define THR2 384
#define NWARP2 (THR2 / 32)      // 12
#define MARGIN 0.5f

__device__ float g_G[B * B];          // Gram matrix scratch
__device__ float g_nrm[B];            // squared norms
__device__ float g_psum[NB];
__device__ float g_pcnt[NB];
__device__ unsigned int g_ticket;     // zero-init; reset by last block

__device__ __forceinline__ void cp_async16(uint32_t dst, const void* src) {
    asm volatile("cp.async.cg.shared.global [%0], [%1], 16;" :: "r"(dst), "l"(src));
}

// ======================= Kernel 1: G = E * E^T (tiled) =======================
__global__ __launch_bounds__(THR1) void gram_kernel(const float* __restrict__ emb)
{
    // trigger FIRST: lets the PDL consumer launch + run its prologue + park in
    // cudaGridDependencySynchronize() while we compute. Memory correctness is
    // carried by the dependency-sync, not by trigger placement.
    cudaTriggerProgrammaticLaunchCompletion();

    __shared__ float4 sA[2][TS * HP4];     // double-buffered k-halves
    __shared__ float4 sB[2][TS * HP4];

    const int tid = threadIdx.x;
    const int ty  = blockIdx.x / GT;
    const int tx  = blockIdx.x % GT;

    const float4* g4 = (const float4*)emb;         // B x 32 float4
    const uint32_t sA0 = (uint32_t)__cvta_generic_to_shared(sA[0]);
    const uint32_t sB0 = (uint32_t)__cvta_generic_to_shared(sB[0]);
    const uint32_t sA1 = (uint32_t)__cvta_generic_to_shared(sA[1]);
    const uint32_t sB1 = (uint32_t)__cvta_generic_to_shared(sB[1]);

    // half h: rows r in [0,32), cols c in [0,16) f4 at global col h*16+c
    // per half per matrix: 512 f4 -> 2 iters of 256 threads
    #pragma unroll
    for (int it = 0; it < 2; it++) {
        int g = tid + THR1 * it;            // 0..511
        int r = g >> 4, c = g & 15;
        uint32_t soff = (uint32_t)((r * HP4 + c) * 16);
        cp_async16(sA0 + soff, g4 + (ty * TS + r) * (D / 4) + c);
        cp_async16(sB0 + soff, g4 + (tx * TS + r) * (D / 4) + c);
    }
    asm volatile("cp.async.commit_group;" ::: "memory");
    #pragma unroll
    for (int it = 0; it < 2; it++) {
        int g = tid + THR1 * it;
        int r = g >> 4, c = g & 15;
        uint32_t soff = (uint32_t)((r * HP4 + c) * 16);
        cp_async16(sA1 + soff, g4 + (ty * TS + r) * (D / 4) + 16 + c);
        cp_async16(sB1 + soff, g4 + (tx * TS + r) * (D / 4) + 16 + c);
    }
    asm volatile("cp.async.commit_group;" ::: "memory");

    const int i  = tid & 31;               // output row within tile
    const int jg = tid >> 5;               // output col group (4 cols)
    float a0 = 0.f, a1 = 0.f, a2 = 0.f, a3 = 0.f;

    asm volatile("cp.async.wait_group 1;" ::: "memory");   // half 0 ready
    __syncthreads();

    #pragma unroll
    for (int h = 0; h < 2; h++) {
        const float4* arow = sA[h] + i * HP4;
        const float4* b0 = sB[h] + (jg * 4 + 0) * HP4;
        const float4* b1 = sB[h] + (jg * 4 + 1) * HP4;
        const float4* b2 = sB[h] + (jg * 4 + 2) * HP4;
        const float4* b3 = sB[h] + (jg * 4 + 3) * HP4;

        #pragma unroll 8
        for (int k = 0; k < D / 8; k++) {          // 16 f4 per half
            float4 x = arow[k];
            float4 p = b0[k];                      // warp-uniform -> broadcast
            a0 = fmaf(x.x, p.x, fmaf(x.y, p.y, fmaf(x.z, p.z, fmaf(x.w, p.w, a0))));
            p = b1[k];
            a1 = fmaf(x.x, p.x, fmaf(x.y, p.y, fmaf(x.z, p.z, fmaf(x.w, p.w, a1))));
            p = b2[k];
            a2 = fmaf(x.x, p.x, fmaf(x.y, p.y, fmaf(x.z, p.z, fmaf(x.w, p.w, a2))));
            p = b3[k];
            a3 = fmaf(x.x, p.x, fmaf(x.y, p.y, fmaf(x.z, p.z, fmaf(x.w, p.w, a3))));
        }

        if (h == 0) {
            asm volatile("cp.async.wait_group 0;" ::: "memory");  // half 1 ready
            __syncthreads();
        }
    }

    // diagonal blocks also emit norms (deterministic shfl tree, coalesced STG)
    if (ty == tx) {
        const int r = tid >> 3;        // 0..31
        const int q = tid & 7;         // 8-lane groups over 8 f4 chunks
        float pp = 0.f;
        #pragma unroll
        for (int hh = 0; hh < 2; hh++) {
            const float4* row = sA[hh] + r * HP4;
            #pragma unroll
            for (int c = 0; c < 2; c++) {
                float4 x = row[q * 2 + c];
                pp = fmaf(x.x, x.x, fmaf(x.y, x.y, fmaf(x.z, x.z, fmaf(x.w, x.w, pp))));
            }
        }
        pp += __shfl_down_sync(0xFFFFFFFFu, pp, 4, 8);
        pp += __shfl_down_sync(0xFFFFFFFFu, pp, 2, 8);
        pp += __shfl_down_sync(0xFFFFFFFFu, pp, 1, 8);
        if (q == 0) g_nrm[ty * TS + r] = pp;
    }

    *(float4*)&g_G[(ty * TS + i) * B + tx * TS + jg * 4] = make_float4(a0, a1, a2, a3);
}

// ================= Kernel 2: triplet reduction from G (PDL consumer) =========
__global__ __launch_bounds__(THR2) void triplet_kernel(
    const int* __restrict__ labels,
    float* __restrict__ out)
{
    __shared__ float snrm[B];
    __shared__ int   slab[B];
    __shared__ float dpos[NA][B];
    __shared__ int   npos[NA];
    __shared__ float rsum[NWARP2];
    __shared__ float rcnt[NWARP2];
    __shared__ int   is_last;

    const int t  = threadIdx.x;      // == column j
    const int ab = blockIdx.x * NA;

    // ---- G-independent prologue (overlaps with gram kernel) ----
    slab[t] = labels[t];
    if (t < NA) npos[t] = 0;

    // ---- wait for gram kernel completion (memory-visible) ----
    cudaGridDependencySynchronize();

    snrm[t] = __ldcg(&g_nrm[t]);             // coalesced 1.5KB read
    __syncthreads();

    const int lt = slab[t];
    float dist[NA];
    #pragma unroll
    for (int aa = 0; aa < NA; aa++) {
        const int a = ab + aa;
        float Gaj = __ldcg(&g_G[a * B + t]);          // coalesced row read
        dist[aa] = fmaxf(snrm[a] - 2.f * Gaj + snrm[t], 0.f);
        if (lt == slab[a] && t != a) {
            int idx = atomicAdd(&npos[aa], 1);
            dpos[aa][idx] = dist[aa];
        }
    }
    __syncthreads();

    float sum = 0.f, cnt = 0.f;
    #pragma unroll
    for (int aa = 0; aa < NA; aa++) {
        if (lt != slab[ab + aa]) {
            const float dn = dist[aa];
            const int np = npos[aa];
            for (int p = 0; p < np; p++) {
                float v = dpos[aa][p] - dn + MARGIN;
                if (v > 1e-16f) { sum += v; cnt += 1.f; }
            }
        }
    }

    // block reduction (12 warps)
    const int lane = t & 31;
    const int warp = t >> 5;
    #pragma unroll
    for (int off = 16; off > 0; off >>= 1) {
        sum += __shfl_down_sync(0xFFFFFFFFu, sum, off);
        cnt += __shfl_down_sync(0xFFFFFFFFu, cnt, off);
    }
    if (lane == 0) { rsum[warp] = sum; rcnt[warp] = cnt; }
    __syncthreads();
    if (warp == 0) {
        float s = (lane < NWARP2) ? rsum[lane] : 0.f;
        float c = (lane < NWARP2) ? rcnt[lane] : 0.f;
        #pragma unroll
        for (int off = 16; off > 0; off >>= 1) {
            s += __shfl_down_sync(0xFFFFFFFFu, s, off);
            c += __shfl_down_sync(0xFFFFFFFFu, c, off);
        }
        if (lane == 0) {
            g_psum[blockIdx.x] = s;
            g_pcnt[blockIdx.x] = c;
        }
    }

    // last-block final reduction
    __threadfence();
    if (t == 0) {
        unsigned int tk = atomicAdd(&g_ticket, 1u);
        is_last = (tk == NB - 1);
    }
    __syncthreads();

    if (is_last && warp == 0) {
        __threadfence();
        volatile float* vs = g_psum;
        volatile float* vc = g_pcnt;
        double s = 0.0, c = 0.0;
        #pragma unroll
        for (int i = lane; i < NB; i += 32) {
            s += (double)vs[i];
            c += (double)vc[i];
        }
        #pragma unroll
        for (int off = 16; off > 0; off >>= 1) {
            s += __shfl_down_sync(0xFFFFFFFFu, s, off);
            c += __shfl_down_sync(0xFFFFFFFFu, c, off);
        }
        if (lane == 0) {
            out[0] = (float)(s / (c + 1e-16));
            g_ticket = 0;                  // reset for graph replay
        }
    }
}

extern "C" void kernel_launch(void* const* d_in, const int* in_sizes, int n_in,
                              void* d_out, int out_size) {
    const float* emb    = (const float*)d_in[0];
    const int*   labels = (const int*)d_in[1];
    float*       out    = (float*)d_out;

    gram_kernel<<<NBLK1, THR1>>>(emb);

    // PDL: triplet_kernel launches while gram_kernel runs; it self-synchronizes
    // via cudaGridDependencySynchronize() before touching g_G / g_nrm.
    cudaLaunchConfig_t cfg = {};
    cfg.gridDim  = dim3(NB, 1, 1);
    cfg.blockDim = dim3(THR2, 1, 1);
    cfg.dynamicSmemBytes = 0;
    cfg.stream = 0;   // legacy default stream (the one the harness captures)
    cudaLaunchAttribute attrs[1];
    attrs[0].id = cudaLaunchAttributeProgrammaticStreamSerialization;
    attrs[0].val.programmaticStreamSerializationAllowed = 1;
    cfg.attrs = attrs;
    cfg.numAttrs = 1;
    cudaLaunchKernelEx(&cfg, triplet_kernel, labels, out);
}

// round 15
// speedup vs baseline: 1.0026x; 1.0026x over previous
#include <cuda_runtime.h>
#include <cuda_bf16.h>
#include <cstdint>

#define B 384
#define D 128
#define TS 32                   // Gram tile size
#define GT (B / TS)             // 12 tiles per dim
#define NBLK1 (GT * GT)         // 144 gram blocks (single wave)
#define THR1 256
#define PITCHF 132              // float pitch per row (128 + 4 pad) -> 16B-aligned rows
#define NA 3
#define NB (B / NA)             // 128 triplet blocks
#define THR2 384
#define NWARP2 (THR2 / 32)      // 12
#define MARGIN 0.5f

__device__ float g_G[B * B];          // Gram matrix scratch
__device__ float g_nrm[B];            // squared norms
__device__ float g_psum[NB];
__device__ float g_pcnt[NB];
__device__ unsigned int g_ticket;     // zero-init; reset by last block

__device__ __forceinline__ float tf32_hi(float x) {
    return __uint_as_float(__float_as_uint(x) & 0xFFFFE000u);
}

__device__ __forceinline__ void mma_tf32(
    float& c0, float& c1, float& c2, float& c3,
    uint32_t a0, uint32_t a1, uint32_t a2, uint32_t a3,
    uint32_t b0, uint32_t b1)
{
    asm volatile(
        "mma.sync.aligned.m16n8k8.row.col.f32.tf32.tf32.f32 "
        "{%0,%1,%2,%3}, {%4,%5,%6,%7}, {%8,%9}, {%0,%1,%2,%3};"
        : "+f"(c0), "+f"(c1), "+f"(c2), "+f"(c3)
        : "r"(a0), "r"(a1), "r"(a2), "r"(a3), "r"(b0), "r"(b1));
}

// ======================= Kernel 1: G = E * E^T (tf32 MMA) ====================
__global__ __launch_bounds__(THR1) void gram_kernel(const float* __restrict__ emb)
{
    // trigger FIRST: PDL consumer launches + parks in dependency-sync
    cudaTriggerProgrammaticLaunchCompletion();

    extern __shared__ float smem[];
    float* aHi = smem;                       // [TS][PITCHF]
    float* aLo = aHi + TS * PITCHF;
    float* bHi = aLo + TS * PITCHF;
    float* bLo = bHi + TS * PITCHF;

    const int tid = threadIdx.x;
    const int ty  = blockIdx.x / GT;
    const int tx  = blockIdx.x % GT;
    const float4* g4 = (const float4*)emb;   // B x 32 float4

    // ---- load + split into tf32 hi/lo (coalesced LDG.128, aligned STS.128) --
    #pragma unroll
    for (int it = 0; it < (TS * (D / 4)) / THR1; it++) {     // 4 iters
        int g  = tid + THR1 * it;            // 0..1023
        int r  = g >> 5, c4 = g & 31;
        float4 va = g4[(ty * TS + r) * (D / 4) + c4];
        float4 vb = g4[(tx * TS + r) * (D / 4) + c4];
        float4 h, l;
        h.x = tf32_hi(va.x); l.x = va.x - h.x;
        h.y = tf32_hi(va.y); l.y = va.y - h.y;
        h.z = tf32_hi(va.z); l.z = va.z - h.z;
        h.w = tf32_hi(va.w); l.w = va.w - h.w;
        *(float4*)&aHi[r * PITCHF + c4 * 4] = h;
        *(float4*)&aLo[r * PITCHF + c4 * 4] = l;
        h.x = tf32_hi(vb.x); l.x = vb.x - h.x;
        h.y = tf32_hi(vb.y); l.y = vb.y - h.y;
        h.z = tf32_hi(vb.z); l.z = vb.z - h.z;
        h.w = tf32_hi(vb.w); l.w = vb.w - h.w;
        *(float4*)&bHi[r * PITCHF + c4 * 4] = h;
        *(float4*)&bLo[r * PITCHF + c4 * 4] = l;
    }
    __syncthreads();

    // ---- exact norms on diagonal blocks: x = hi + lo exactly, same order
    //      as the R13 shfl-tree -> bit-identical g_nrm ----
    if (ty == tx) {
        const int r = tid >> 3;              // 0..31
        const int q = tid & 7;               // 8 chunks of 16 floats
        float pp = 0.f;
        #pragma unroll
        for (int c = 0; c < 4; c++) {
            const float4 h = *(const float4*)&aHi[r * PITCHF + (q * 4 + c) * 4];
            const float4 l = *(const float4*)&aLo[r * PITCHF + (q * 4 + c) * 4];
            float x0 = h.x + l.x, x1 = h.y + l.y, x2 = h.z + l.z, x3 = h.w + l.w;
            pp = fmaf(x0, x0, fmaf(x1, x1, fmaf(x2, x2, fmaf(x3, x3, pp))));
        }
        pp += __shfl_down_sync(0xFFFFFFFFu, pp, 4, 8);
        pp += __shfl_down_sync(0xFFFFFFFFu, pp, 2, 8);
        pp += __shfl_down_sync(0xFFFFFFFFu, pp, 1, 8);
        if (q == 0) g_nrm[ty * TS + r] = pp;
    }

    // ---- MMA: warp w owns 16x8 tile (m0 = (w&1)*16, n0 = (w>>1)*8) ----
    const int wid  = tid >> 5;
    const int lane = tid & 31;
    const int grp  = lane >> 2;              // 0..7
    const int t4   = lane & 3;               // 0..3
    const int m0   = (wid & 1) * 16;
    const int n0   = (wid >> 1) * 8;

    float c0 = 0.f, c1 = 0.f, c2 = 0.f, c3 = 0.f;

    const int ra0 = (m0 + grp) * PITCHF;     // A rows: grp, grp+8
    const int ra1 = (m0 + grp + 8) * PITCHF;
    const int rb  = (n0 + grp) * PITCHF;     // B row (n-index): grp

    #pragma unroll
    for (int ks = 0; ks < D / 8; ks++) {
        const int k0 = ks * 8;
        // A fragments (row-major 16x8): a0=[g][t], a1=[g+8][t], a2=[g][t+4], a3=[g+8][t+4]
        uint32_t ah0 = __float_as_uint(aHi[ra0 + k0 + t4]);
        uint32_t ah1 = __float_as_uint(aHi[ra1 + k0 + t4]);
        uint32_t ah2 = __float_as_uint(aHi[ra0 + k0 + t4 + 4]);
        uint32_t ah3 = __float_as_uint(aHi[ra1 + k0 + t4 + 4]);
        uint32_t al0 = __float_as_uint(aLo[ra0 + k0 + t4]);
        uint32_t al1 = __float_as_uint(aLo[ra1 + k0 + t4]);
        uint32_t al2 = __float_as_uint(aLo[ra0 + k0 + t4 + 4]);
        uint32_t al3 = __float_as_uint(aLo[ra1 + k0 + t4 + 4]);
        // B fragments (col-major 8x8): b0=[k=t][n=g], b1=[k=t+4][n=g]
        uint32_t bh0 = __float_as_uint(bHi[rb + k0 + t4]);
        uint32_t bh1 = __float_as_uint(bHi[rb + k0 + t4 + 4]);
        uint32_t bl0 = __float_as_uint(bLo[rb + k0 + t4]);
        uint32_t bl1 = __float_as_uint(bLo[rb + k0 + t4 + 4]);

        mma_tf32(c0, c1, c2, c3, ah0, ah1, ah2, ah3, bh0, bh1);   // hi*hi
        mma_tf32(c0, c1, c2, c3, ah0, ah1, ah2, ah3, bl0, bl1);   // hi*lo
        mma_tf32(c0, c1, c2, c3, al0, al1, al2, al3, bh0, bh1);   // lo*hi
    }

    // ---- epilogue: D element (row, col) mapping of m16n8 accumulators ----
    const int gr0 = ty * TS + m0 + grp;
    const int gr1 = gr0 + 8;
    const int gc  = tx * TS + n0 + 2 * t4;
    *(float2*)&g_G[gr0 * B + gc] = make_float2(c0, c1);
    *(float2*)&g_G[gr1 * B + gc] = make_float2(c2, c3);
}

// ================= Kernel 2: triplet reduction from G (PDL consumer) =========
__global__ __launch_bounds__(THR2) void triplet_kernel(
    const int* __restrict__ labels,
    float* __restrict__ out)
{
    __shared__ float snrm[B];
    __shared__ int   slab[B];
    __shared__ float dpos[NA][B];
    __shared__ int   npos[NA];
    __shared__ float rsum[NWARP2];
    __shared__ float rcnt[NWARP2];
    __shared__ int   is_last;

    const int t  = threadIdx.x;      // == column j
    const int ab = blockIdx.x * NA;

    // ---- G-independent prologue (overlaps with gram kernel) ----
    slab[t] = labels[t];
    if (t < NA) npos[t] = 0;

    // ---- wait for gram kernel completion (memory-visible) ----
    cudaGridDependencySynchronize();

    snrm[t] = __ldcg(&g_nrm[t]);             // coalesced 1.5KB read
    __syncthreads();

    const int lt = slab[t];
    float dist[NA];
    #pragma unroll
    for (int aa = 0; aa < NA; aa++) {
        const int a = ab + aa;
        float Gaj = __ldcg(&g_G[a * B + t]);          // coalesced row read
        dist[aa] = fmaxf(snrm[a] - 2.f * Gaj + snrm[t], 0.f);
        if (lt == slab[a] && t != a) {
            int idx = atomicAdd(&npos[aa], 1);
            dpos[aa][idx] = dist[aa];
        }
    }
    __syncthreads();

    float sum = 0.f, cnt = 0.f;
    #pragma unroll
    for (int aa = 0; aa < NA; aa++) {
        if (lt != slab[ab + aa]) {
            const float dn = dist[aa];
            const int np = npos[aa];
            for (int p = 0; p < np; p++) {
                float v = dpos[aa][p] - dn + MARGIN;
                if (v > 1e-16f) { sum += v; cnt += 1.f; }
            }
        }
    }

    // block reduction (12 warps)
    const int lane = t & 31;
    const int warp = t >> 5;
    #pragma unroll
    for (int off = 16; off > 0; off >>= 1) {
        sum += __shfl_down_sync(0xFFFFFFFFu, sum, off);
        cnt += __shfl_down_sync(0xFFFFFFFFu, cnt, off);
    }
    if (lane == 0) { rsum[warp] = sum; rcnt[warp] = cnt; }
    __syncthreads();
    if (warp == 0) {
        float s = (lane < NWARP2) ? rsum[lane] : 0.f;
        float c = (lane < NWARP2) ? rcnt[lane] : 0.f;
        #pragma unroll
        for (int off = 16; off > 0; off >>= 1) {
            s += __shfl_down_sync(0xFFFFFFFFu, s, off);
            c += __shfl_down_sync(0xFFFFFFFFu, c, off);
        }
        if (lane == 0) {
            g_psum[blockIdx.x] = s;
            g_pcnt[blockIdx.x] = c;
        }
    }

    // last-block final reduction
    __threadfence();
    if (t == 0) {
        unsigned int tk = atomicAdd(&g_ticket, 1u);
        is_last = (tk == NB - 1);
    }
    __syncthreads();

    if (is_last && warp == 0) {
        __threadfence();
        volatile float* vs = g_psum;
        volatile float* vc = g_pcnt;
        double s = 0.0, c = 0.0;
        #pragma unroll
        for (int i = lane; i < NB; i += 32) {
            s += (double)vs[i];
            c += (double)vc[i];
        }
        #pragma unroll
        for (int off = 16; off > 0; off >>= 1) {
            s += __shfl_down_sync(0xFFFFFFFFu, s, off);
            c += __shfl_down_sync(0xFFFFFFFFu, c, off);
        }
        if (lane == 0) {
            out[0] = (float)(s / (c + 1e-16));
            g_ticket = 0;                  // reset for graph replay
        }
    }
}

extern "C" void kernel_launch(void* const* d_in, const int* in_sizes, int n_in,
                              void* d_out, int out_size) {
    const float* emb    = (const float*)d_in[0];
    const int*   labels = (const int*)d_in[1];
    float*       out    = (float*)d_out;

    const size_t smem1 = (size_t)4 * TS * PITCHF * sizeof(float);   // 67,584 B
    cudaFuncSetAttribute(gram_kernel,
                         cudaFuncAttributeMaxDynamicSharedMemorySize, (int)smem1);

    gram_kernel<<<NBLK1, THR1, smem1>>>(emb);

    // PDL: triplet_kernel launches while gram_kernel runs; it self-synchronizes
    // via cudaGridDependencySynchronize() before touching g_G / g_nrm.
    cudaLaunchConfig_t cfg = {};
    cfg.gridDim  = dim3(NB, 1, 1);
    cfg.blockDim = dim3(THR2, 1, 1);
    cfg.dynamicSmemBytes = 0;
    cfg.stream = 0;   // legacy default stream (the one the harness captures)
    cudaLaunchAttribute attrs[1];
    attrs[0].id = cudaLaunchAttributeProgrammaticStreamSerialization;
    attrs[0].val.programmaticStreamSerializationAllowed = 1;
    cfg.attrs = attrs;
    cfg.numAttrs = 1;
    cudaLaunchKernelEx(&cfg, triplet_kernel, labels, out);
}